// round 16
// baseline (speedup 1.0000x reference)
#include <cuda_runtime.h>
#include <math.h>

// ---------------------------------------------------------------------------
// Shapes: B=32, OBS=768, D=512, V=64
// Outputs (float32): h(32*512) pred(32*768) graph(64*64) reasoning(32*512)
//
// SINGLE persistent kernel, grid = occ_blocks_per_SM * numSMs (queried at
// launch; grid_sync uses gridDim.x -> residency-safe). launch_bounds(256,3).
// Phases (monotonic grid barriers, replay-safe):
//  P0: enc1(T1) + EA + EB + zero(graph)   (2561 units)
//  P1: enc2 -> Z                          (256 units)
//  P2: GI = [Z|action] @ wih^T + bih      (768 units)
//  P3: GRU pointwise -> H, HA, out_h
//  P4: dec(pred) + rs1(R1) + CC           (1152 units)
//  P5: score (512 units: b x 4 rows, warp = row x d-half) + rs2 (256 units)
// ---------------------------------------------------------------------------

#define NB 32
#define ND 512
#define NV 64

#define OFF_T1   0          // 32*1024
#define OFF_Z    32768      // 32*512
#define OFF_GI   49152      // 32*1536
#define OFF_H    98304      // 32*512
#define OFF_HA   114688     // 32*512
#define OFF_CC   131072     // 32*1024
#define OFF_EA   163840     // 64*1024
#define OFF_EB   229376     // 64*1024
#define OFF_R1   294912     // 32*512
#define SCRATCH_FLOATS 311296

__device__ float g_scratch[SCRATCH_FLOATS];
__device__ int   g_bars[8];   // monotonic grid-barrier counters (never reset)

// ---------------------------------------------------------------------------
__device__ __forceinline__ float tanh_approx(float x) {
    float y;
    asm("tanh.approx.f32 %0, %1;" : "=f"(y) : "f"(x));
    return y;
}
__device__ __forceinline__ float sigmoid_acc(float x) {
    return 1.0f / (1.0f + expf(-x));
}
__device__ __forceinline__ float gelu_exact(float x) {
    return 0.5f * x * (1.0f + erff(x * 0.70710678118654752f));
}

// Monotonic grid barrier (uses gridDim.x; grid size is identical every launch)
__device__ __forceinline__ void grid_sync(int i) {
    __syncthreads();
    if (threadIdx.x == 0) {
        const int nb = (int)gridDim.x;
        __threadfence();
        int old = atomicAdd(&g_bars[i], 1);
        int target = old - (old % nb) + nb;
        while (*((volatile int*)&g_bars[i]) < target) __nanosleep(64);
        __threadfence();
    }
    __syncthreads();
}

// ---------------------------------------------------------------------------
// Split-K warp partial dot: lanes cover k = p + lane*4 (float4); 4-deep A
// batches (fits 85-reg budget at occ 3); shuffle fold -> m = lane.
// ---------------------------------------------------------------------------
#define FOLD(W, HALF) { \
    _Pragma("unroll") \
    for (int i = 0; i < HALF; i++) { \
        bool hi = (lane & W) != 0; \
        float send = hi ? acc[i] : acc[HALF + i]; \
        float recv = __shfl_xor_sync(0xffffffffu, send, W); \
        acc[i] = (hi ? acc[HALF + i] : acc[i]) + recv; \
    } }

template<int KS>
__device__ __forceinline__ float splitk_warp(
    const float* __restrict__ A, int lda,
    const float* __restrict__ wrow, int lane)
{
    float acc[32];
    #pragma unroll
    for (int i = 0; i < 32; i++) acc[i] = 0.f;

    #pragma unroll
    for (int p = 0; p < KS; p += 128) {
        const int rem = KS - p;
        const bool on = (lane * 4) < rem;
        const int k = p + lane * 4;
        float4 w4 = on ? *reinterpret_cast<const float4*>(wrow + k)
                       : make_float4(0.f, 0.f, 0.f, 0.f);
        #pragma unroll
        for (int b = 0; b < 8; b++) {
            float4 a4[4];
            #pragma unroll
            for (int i = 0; i < 4; i++) {
                a4[i] = on ? *reinterpret_cast<const float4*>(A + (b * 4 + i) * lda + k)
                           : make_float4(0.f, 0.f, 0.f, 0.f);
            }
            #pragma unroll
            for (int i = 0; i < 4; i++) {
                int m = b * 4 + i;
                acc[m] = fmaf(a4[i].x, w4.x, acc[m]);
                acc[m] = fmaf(a4[i].y, w4.y, acc[m]);
                acc[m] = fmaf(a4[i].z, w4.z, acc[m]);
                acc[m] = fmaf(a4[i].w, w4.w, acc[m]);
            }
        }
    }
    FOLD(16, 16) FOLD(8, 8) FOLD(4, 4) FOLD(2, 2) FOLD(1, 1)
    return acc[0];
}

// smem pool: score needs 128*66 + 4*128 + 128 + 512 = 9600 floats (38.4 KB)
#define SE_PITCH 66
#define POOL_FLOATS (128*SE_PITCH + 4*128 + 128 + 512)

// ---------------------------------------------------------------------------
__global__ void __launch_bounds__(256, 3) mega_kernel(
    const float* __restrict__ obs, const float* __restrict__ action,
    const float* __restrict__ embed,
    const float* __restrict__ sc_w1, const float* __restrict__ sc_b1,
    const float* __restrict__ sc_w2, const float* __restrict__ sc_b2,
    const float* __restrict__ enc_w1, const float* __restrict__ enc_b1,
    const float* __restrict__ enc_w2, const float* __restrict__ enc_b2,
    const float* __restrict__ gru_wih, const float* __restrict__ gru_bih,
    const float* __restrict__ gru_bhh,
    const float* __restrict__ dec_w, const float* __restrict__ dec_b,
    const float* __restrict__ rs_w1, const float* __restrict__ rs_b1,
    const float* __restrict__ rs_w2, const float* __restrict__ rs_b2,
    float* __restrict__ T1, float* __restrict__ Z, float* __restrict__ GI,
    float* __restrict__ H, float* __restrict__ HA, float* __restrict__ CC,
    float* __restrict__ EA, float* __restrict__ EB, float* __restrict__ R1,
    float* __restrict__ out_h, float* __restrict__ out_pred,
    float* __restrict__ out_graph, float* __restrict__ out_reason)
{
    __shared__ float pool[POOL_FLOATS];
    const int bid  = blockIdx.x;
    const int NBLK = (int)gridDim.x;
    const int tid  = threadIdx.x;
    const int warp = tid >> 5, lane = tid & 31;
    const int ns = warp >> 2, s = warp & 3;     // GEMM units: n-sub, slice

    // ---------------- P0: enc1 (512) + EA (1024) + EB (1024) + zero (1) ----
    for (int u = bid; u < 2561; u += NBLK) {
        if (u == 2560) {
            for (int i = tid; i < NV * NV; i += 256) out_graph[i] = 0.0f;
            continue;
        }
        float val;
        if (u < 512) {
            int n = u * 2 + ns;
            val = splitk_warp<192>(obs + s * 192, 768, enc_w1 + n * 768 + s * 192, lane);
        } else if (u < 1536) {
            int b2 = u - 512;
            int mg = b2 & 1;
            int n  = (b2 >> 1) * 2 + ns;
            val = splitk_warp<128>(embed + mg * 32 * 512 + s * 128, 512,
                                   sc_w1 + n * 1536 + s * 128, lane);
        } else {
            int b2 = u - 1536;
            int mg = b2 & 1;
            int n  = (b2 >> 1) * 2 + ns;
            val = splitk_warp<128>(embed + mg * 32 * 512 + s * 128, 512,
                                   sc_w1 + n * 1536 + 512 + s * 128, lane);
        }
        pool[warp * 33 + lane] = val;
        __syncthreads();
        if (tid < 64) {
            int m = tid & 31, nn = tid >> 5;
            float v = pool[(nn * 4 + 0) * 33 + m] + pool[(nn * 4 + 1) * 33 + m]
                    + pool[(nn * 4 + 2) * 33 + m] + pool[(nn * 4 + 3) * 33 + m];
            if (u < 512) {
                int n = u * 2 + nn;
                T1[m * 1024 + n] = gelu_exact(v + enc_b1[n]);
            } else if (u < 1536) {
                int b2 = u - 512;
                int mg = b2 & 1;
                int n  = (b2 >> 1) * 2 + nn;
                EA[(mg * 32 + m) * 1024 + n] = v + sc_b1[n];
            } else {
                int b2 = u - 1536;
                int mg = b2 & 1;
                int n  = (b2 >> 1) * 2 + nn;
                EB[(mg * 32 + m) * 1024 + n] = v;
            }
        }
        __syncthreads();
    }
    grid_sync(0);

    // ---------------- P1: enc2 -> Z (256 units) ----------------------------
    for (int u = bid; u < 256; u += NBLK) {
        int n = u * 2 + ns;
        float val = splitk_warp<256>(T1 + s * 256, 1024, enc_w2 + n * 1024 + s * 256, lane);
        pool[warp * 33 + lane] = val;
        __syncthreads();
        if (tid < 64) {
            int m = tid & 31, nn = tid >> 5;
            float v = pool[(nn * 4 + 0) * 33 + m] + pool[(nn * 4 + 1) * 33 + m]
                    + pool[(nn * 4 + 2) * 33 + m] + pool[(nn * 4 + 3) * 33 + m];
            int n2 = u * 2 + nn;
            Z[m * 512 + n2] = v + enc_b2[n2];
        }
        __syncthreads();
    }
    grid_sync(1);

    // ---------------- P2: GI (768 units) -----------------------------------
    for (int u = bid; u < 768; u += NBLK) {
        int n = u * 2 + ns;
        const float* Asl = (s < 2) ? (Z + s * 256) : (action + (s - 2) * 256);
        float val = splitk_warp<256>(Asl, 512, gru_wih + n * 1024 + s * 256, lane);
        pool[warp * 33 + lane] = val;
        __syncthreads();
        if (tid < 64) {
            int m = tid & 31, nn = tid >> 5;
            float v = pool[(nn * 4 + 0) * 33 + m] + pool[(nn * 4 + 1) * 33 + m]
                    + pool[(nn * 4 + 2) * 33 + m] + pool[(nn * 4 + 3) * 33 + m];
            int n2 = u * 2 + nn;
            GI[m * 1536 + n2] = v + gru_bih[n2];
        }
        __syncthreads();
    }
    grid_sync(2);

    // ---------------- P3: GRU pointwise (h0=0 => gh=bhh, h=(1-u)*n) --------
    {
        int i = bid * 256 + tid;
        if (i < NB * ND) {
            int b = i >> 9, d = i & 511;
            const float* gi = GI + b * 1536;
            float r  = sigmoid_acc(gi[d]        + gru_bhh[d]);
            float uu = sigmoid_acc(gi[512 + d]  + gru_bhh[512 + d]);
            float nn = tanhf(gi[1024 + d] + r * gru_bhh[1024 + d]);
            float h  = (1.0f - uu) * nn;
            H[i] = h;
            out_h[i] = h;
            HA[i] = h + action[i];
        }
    }
    grid_sync(3);

    // ---------------- P4: dec (384) + rs1 (256) + CC (512) = 1152 ----------
    for (int u = bid; u < 1152; u += NBLK) {
        float val;
        if (u < 384) {
            int n = u * 2 + ns;
            val = splitk_warp<128>(H + s * 128, 512, dec_w + n * 512 + s * 128, lane);
        } else if (u < 640) {
            int n = (u - 384) * 2 + ns;
            val = splitk_warp<128>(H + s * 128, 512, rs_w1 + n * 512 + s * 128, lane);
        } else {
            int n = (u - 640) * 2 + ns;
            val = splitk_warp<128>(HA + s * 128, 512, sc_w1 + n * 1536 + 1024 + s * 128, lane);
        }
        pool[warp * 33 + lane] = val;
        __syncthreads();
        if (tid < 64) {
            int m = tid & 31, nn = tid >> 5;
            float v = pool[(nn * 4 + 0) * 33 + m] + pool[(nn * 4 + 1) * 33 + m]
                    + pool[(nn * 4 + 2) * 33 + m] + pool[(nn * 4 + 3) * 33 + m];
            if (u < 384) {
                int n = u * 2 + nn;
                out_pred[m * 768 + n] = v + dec_b[n];
            } else if (u < 640) {
                int n = (u - 384) * 2 + nn;
                R1[m * 512 + n] = gelu_exact(v + rs_b1[n]);
            } else {
                int n = (u - 640) * 2 + nn;
                CC[m * 1024 + n] = v;
            }
        }
        __syncthreads();
    }
    grid_sync(4);

    // ---------------- P5: score (512 units) + rs2 (256 units) --------------
    // Score unit u<512: b = u>>4, i0 = (u&15)*4. 8 warps: row r = warp&3,
    // d-half dh = warp>>2. Thread covers j = 2*lane, 2*lane+1 (LDS.64 from
    // sE, pitch 66). Per-thread (acc, lin) over its d-half; d-half pairs
    // combined via smem; warp dh==0 writes sigmoid/32 via atomicAdd.
    float* sE   = pool;                          // [dd][j] 128 x SE_PITCH
    float* sA4  = pool + 128 * SE_PITCH;         // [4][128]
    float* sW   = pool + 128 * SE_PITCH + 512;   // [128]
    float* sRed = pool + 128 * SE_PITCH + 640;   // [4*32*4]

    const float C0 = 0.79788456080286536f;   // sqrt(2/pi)
    const float C1 = 0.03567740813636141f;   // sqrt(2/pi)*0.044715

    for (int u = bid; u < 768; u += NBLK) {
        if (u < 512) {
            const int b   = u >> 4;
            const int i0  = (u & 15) * 4;
            const int r   = warp & 3;
            const int dh  = warp >> 2;
            const int jp  = lane * 2;

            float acca = 0.f, accb = 0.f, lina = 0.f, linb = 0.f;

            for (int d0 = 0; d0 < 1024; d0 += 128) {
                for (int idx = tid; idx < 64 * 128; idx += 256) {
                    int j = idx >> 7, dd = idx & 127;
                    sE[dd * SE_PITCH + j] = EB[j * 1024 + d0 + dd];
                }
                for (int idx = tid; idx < 4 * 128; idx += 256) {
                    int rr = idx >> 7, dd = idx & 127;
                    sA4[rr * 128 + dd] = EA[(i0 + rr) * 1024 + d0 + dd]
                                       + CC[b * 1024 + d0 + dd];
                }
                if (tid < 128) sW[tid] = 0.5f * sc_w2[d0 + tid];
                __syncthreads();

                const int dlo = dh * 64, dhi = dlo + 64;
                #pragma unroll 4
                for (int dd = dlo; dd < dhi; dd++) {
                    float2 e = *reinterpret_cast<const float2*>(&sE[dd * SE_PITCH + jp]);
                    float a  = sA4[r * 128 + dd];
                    float w  = sW[dd];

                    float xa = a + e.x, xb = a + e.y;
                    float ta = xa * fmaf(C1, xa * xa, C0);
                    float tb = xb * fmaf(C1, xb * xb, C0);
                    float ha = tanh_approx(ta);
                    float hb = tanh_approx(tb);
                    float wxa = w * xa, wxb = w * xb;
                    acca = fmaf(wxa, ha, acca);  lina += wxa;
                    accb = fmaf(wxb, hb, accb);  linb += wxb;
                }
                __syncthreads();
            }

            if (dh == 1) {
                int o = (r * 32 + lane) * 4;
                sRed[o] = acca; sRed[o + 1] = accb;
                sRed[o + 2] = lina; sRed[o + 3] = linb;
            }
            __syncthreads();
            if (dh == 0) {
                int o = (r * 32 + lane) * 4;
                acca += sRed[o];     accb += sRed[o + 1];
                lina += sRed[o + 2]; linb += sRed[o + 3];
                const float b2 = sc_b2[0];
                float sa = sigmoid_acc(acca + lina + b2) * (1.0f / 32.0f);
                float sb = sigmoid_acc(accb + linb + b2) * (1.0f / 32.0f);
                atomicAdd(&out_graph[(i0 + r) * 64 + jp],     sa);
                atomicAdd(&out_graph[(i0 + r) * 64 + jp + 1], sb);
            }
            __syncthreads();
        } else {
            // rs2 unit
            int n = (u - 512) * 2 + ns;
            float val = splitk_warp<128>(R1 + s * 128, 512, rs_w2 + n * 512 + s * 128, lane);
            pool[warp * 33 + lane] = val;
            __syncthreads();
            if (tid < 64) {
                int m = tid & 31, nn = tid >> 5;
                float v = pool[(nn * 4 + 0) * 33 + m] + pool[(nn * 4 + 1) * 33 + m]
                        + pool[(nn * 4 + 2) * 33 + m] + pool[(nn * 4 + 3) * 33 + m];
                int n2 = (u - 512) * 2 + nn;
                out_reason[m * 512 + n2] = v + rs_b2[n2];
            }
            __syncthreads();
        }
    }
}

// ---------------------------------------------------------------------------
extern "C" void kernel_launch(void* const* d_in, const int* in_sizes, int n_in,
                              void* d_out, int out_size)
{
    float* S = nullptr;
    cudaGetSymbolAddress((void**)&S, g_scratch);

    const float* obs     = (const float*)d_in[0];
    const float* action  = (const float*)d_in[1];
    const float* embed   = (const float*)d_in[2];
    const float* sc_w1   = (const float*)d_in[3];
    const float* sc_b1   = (const float*)d_in[4];
    const float* sc_w2   = (const float*)d_in[5];
    const float* sc_b2   = (const float*)d_in[6];
    const float* enc_w1  = (const float*)d_in[7];
    const float* enc_b1  = (const float*)d_in[8];
    const float* enc_w2  = (const float*)d_in[9];
    const float* enc_b2  = (const float*)d_in[10];
    const float* gru_wih = (const float*)d_in[11];
    // d_in[12] gru_whh unused (h0 == 0)
    const float* gru_bih = (const float*)d_in[13];
    const float* gru_bhh = (const float*)d_in[14];
    const float* dec_w   = (const float*)d_in[15];
    const float* dec_b   = (const float*)d_in[16];
    const float* rs_w1   = (const float*)d_in[17];
    const float* rs_b1   = (const float*)d_in[18];
    const float* rs_w2   = (const float*)d_in[19];
    const float* rs_b2   = (const float*)d_in[20];

    float* out        = (float*)d_out;
    float* out_h      = out;
    float* out_pred   = out + 16384;
    float* out_graph  = out + 16384 + 24576;
    float* out_reason = out + 16384 + 24576 + 4096;

    float* T1 = S + OFF_T1;
    float* Z  = S + OFF_Z;
    float* GI = S + OFF_GI;
    float* H  = S + OFF_H;
    float* HA = S + OFF_HA;
    float* CC = S + OFF_CC;
    float* EA = S + OFF_EA;
    float* EB = S + OFF_EB;
    float* R1 = S + OFF_R1;

    // Residency-safe grid: query occupancy (host-side, deterministic,
    // capture-legal) and size the persistent grid to exactly fit.
    int dev = 0;
    cudaGetDevice(&dev);
    int smc = 148;
    cudaDeviceGetAttribute(&smc, cudaDevAttrMultiProcessorCount, dev);
    int nb = 1;
    cudaOccupancyMaxActiveBlocksPerMultiprocessor(&nb, mega_kernel, 256, 0);
    if (nb < 1) nb = 1;
    if (nb > 3) nb = 3;
    int grid = nb * smc;

    mega_kernel<<<grid, 256>>>(
        obs, action, embed,
        sc_w1, sc_b1, sc_w2, sc_b2,
        enc_w1, enc_b1, enc_w2, enc_b2,
        gru_wih, gru_bih, gru_bhh,
        dec_w, dec_b, rs_w1, rs_b1, rs_w2, rs_b2,
        T1, Z, GI, H, HA, CC, EA, EB, R1,
        out_h, out_pred, out_graph, out_reason);
}

// round 17
// speedup vs baseline: 1.4714x; 1.4714x over previous
#include <cuda_runtime.h>
#include <math.h>

// ---------------------------------------------------------------------------
// Shapes: B=32, OBS=768, D=512, V=64
// Outputs (float32): h(32*512) pred(32*768) graph(64*64) reasoning(32*512)
//
// SINGLE persistent kernel, 296 blocks (2/SM x 148) x 256 threads.
// Phases separated by monotonic grid barriers (replay-safe):
//  P0 : enc1(T1) + EA + EB + zero(graph)   (2561 units)
//  P1 : enc2 -> Z                          (256 units)
//  P2 : GI = [Z|action] @ wih^T + bih      (768 units)
//  P3 : GRU pointwise -> H, HA, out_h
//  P4 : dec(pred) + rs1(R1) + CC           (1152 units)
//  P4b: dots da/db/dc (160 warp-dots)      (20 block-units)
//  P5 : score (256 units of 8 i-rows; lin removed) + rs2 (256 units)
// ---------------------------------------------------------------------------

#define NB 32
#define ND 512
#define NV 64
#define NBLK 296

#define OFF_T1   0          // 32*1024
#define OFF_Z    32768      // 32*512
#define OFF_GI   49152      // 32*1536
#define OFF_H    98304      // 32*512
#define OFF_HA   114688     // 32*512
#define OFF_CC   131072     // 32*1024
#define OFF_EA   163840     // 64*1024
#define OFF_EB   229376     // 64*1024
#define OFF_R1   294912     // 32*512
#define OFF_DA   311296     // 64
#define OFF_DB   311360     // 64
#define OFF_DC   311424     // 32
#define SCRATCH_FLOATS 311456

__device__ float g_scratch[SCRATCH_FLOATS];
__device__ int   g_bars[8];   // monotonic grid-barrier counters (never reset)

// ---------------------------------------------------------------------------
__device__ __forceinline__ float tanh_approx(float x) {
    float y;
    asm("tanh.approx.f32 %0, %1;" : "=f"(y) : "f"(x));
    return y;
}
__device__ __forceinline__ float sigmoid_acc(float x) {
    return 1.0f / (1.0f + expf(-x));
}
__device__ __forceinline__ float gelu_exact(float x) {
    return 0.5f * x * (1.0f + erff(x * 0.70710678118654752f));
}

// Monotonic grid barrier: each launch adds exactly NBLK to counter i.
__device__ __forceinline__ void grid_sync(int i) {
    __syncthreads();
    if (threadIdx.x == 0) {
        __threadfence();
        int old = atomicAdd(&g_bars[i], 1);
        int target = old - (old % NBLK) + NBLK;
        while (*((volatile int*)&g_bars[i]) < target) __nanosleep(64);
        __threadfence();
    }
    __syncthreads();
}

// ---------------------------------------------------------------------------
// Split-K warp partial dot (R14/R15): lanes cover k = p + lane*4 (float4);
// 8-deep A batches; shuffle fold -> m = lane.
// ---------------------------------------------------------------------------
#define FOLD(W, HALF) { \
    _Pragma("unroll") \
    for (int i = 0; i < HALF; i++) { \
        bool hi = (lane & W) != 0; \
        float send = hi ? acc[i] : acc[HALF + i]; \
        float recv = __shfl_xor_sync(0xffffffffu, send, W); \
        acc[i] = (hi ? acc[HALF + i] : acc[i]) + recv; \
    } }

template<int KS>
__device__ __forceinline__ float splitk_warp(
    const float* __restrict__ A, int lda,
    const float* __restrict__ wrow, int lane)
{
    float acc[32];
    #pragma unroll
    for (int i = 0; i < 32; i++) acc[i] = 0.f;

    #pragma unroll
    for (int p = 0; p < KS; p += 128) {
        const int rem = KS - p;
        const bool on = (lane * 4) < rem;
        const int k = p + lane * 4;
        float4 w4 = on ? *reinterpret_cast<const float4*>(wrow + k)
                       : make_float4(0.f, 0.f, 0.f, 0.f);
        #pragma unroll
        for (int b = 0; b < 4; b++) {
            float4 a4[8];
            #pragma unroll
            for (int i = 0; i < 8; i++) {
                a4[i] = on ? *reinterpret_cast<const float4*>(A + (b * 8 + i) * lda + k)
                           : make_float4(0.f, 0.f, 0.f, 0.f);
            }
            #pragma unroll
            for (int i = 0; i < 8; i++) {
                int m = b * 8 + i;
                acc[m] = fmaf(a4[i].x, w4.x, acc[m]);
                acc[m] = fmaf(a4[i].y, w4.y, acc[m]);
                acc[m] = fmaf(a4[i].z, w4.z, acc[m]);
                acc[m] = fmaf(a4[i].w, w4.w, acc[m]);
            }
        }
    }
    FOLD(16, 16) FOLD(8, 8) FOLD(4, 4) FOLD(2, 2) FOLD(1, 1)
    return acc[0];
}

// smem pool: score needs 128*66 + 8*128 + 128 = 9600 floats (38.4 KB)
#define SE_PITCH 66
#define POOL_FLOATS (128*SE_PITCH + 8*128 + 128)

// ---------------------------------------------------------------------------
__global__ void __launch_bounds__(256, 2) mega_kernel(
    const float* __restrict__ obs, const float* __restrict__ action,
    const float* __restrict__ embed,
    const float* __restrict__ sc_w1, const float* __restrict__ sc_b1,
    const float* __restrict__ sc_w2, const float* __restrict__ sc_b2,
    const float* __restrict__ enc_w1, const float* __restrict__ enc_b1,
    const float* __restrict__ enc_w2, const float* __restrict__ enc_b2,
    const float* __restrict__ gru_wih, const float* __restrict__ gru_bih,
    const float* __restrict__ gru_bhh,
    const float* __restrict__ dec_w, const float* __restrict__ dec_b,
    const float* __restrict__ rs_w1, const float* __restrict__ rs_b1,
    const float* __restrict__ rs_w2, const float* __restrict__ rs_b2,
    float* __restrict__ T1, float* __restrict__ Z, float* __restrict__ GI,
    float* __restrict__ H, float* __restrict__ HA, float* __restrict__ CC,
    float* __restrict__ EA, float* __restrict__ EB, float* __restrict__ R1,
    float* __restrict__ DA, float* __restrict__ DB, float* __restrict__ DC,
    float* __restrict__ out_h, float* __restrict__ out_pred,
    float* __restrict__ out_graph, float* __restrict__ out_reason)
{
    __shared__ float pool[POOL_FLOATS];
    const int bid  = blockIdx.x;
    const int tid  = threadIdx.x;
    const int warp = tid >> 5, lane = tid & 31;
    const int ns = warp >> 2, s = warp & 3;     // GEMM units: n-sub, slice

    // ---------------- P0: enc1 (512) + EA (1024) + EB (1024) + zero (1) ----
    for (int u = bid; u < 2561; u += NBLK) {
        if (u == 2560) {
            for (int i = tid; i < NV * NV; i += 256) out_graph[i] = 0.0f;
            continue;
        }
        float val;
        if (u < 512) {
            int n = u * 2 + ns;
            val = splitk_warp<192>(obs + s * 192, 768, enc_w1 + n * 768 + s * 192, lane);
        } else if (u < 1536) {
            int b2 = u - 512;
            int mg = b2 & 1;
            int n  = (b2 >> 1) * 2 + ns;
            val = splitk_warp<128>(embed + mg * 32 * 512 + s * 128, 512,
                                   sc_w1 + n * 1536 + s * 128, lane);
        } else {
            int b2 = u - 1536;
            int mg = b2 & 1;
            int n  = (b2 >> 1) * 2 + ns;
            val = splitk_warp<128>(embed + mg * 32 * 512 + s * 128, 512,
                                   sc_w1 + n * 1536 + 512 + s * 128, lane);
        }
        pool[warp * 33 + lane] = val;
        __syncthreads();
        if (tid < 64) {
            int m = tid & 31, nn = tid >> 5;
            float v = pool[(nn * 4 + 0) * 33 + m] + pool[(nn * 4 + 1) * 33 + m]
                    + pool[(nn * 4 + 2) * 33 + m] + pool[(nn * 4 + 3) * 33 + m];
            if (u < 512) {
                int n = u * 2 + nn;
                T1[m * 1024 + n] = gelu_exact(v + enc_b1[n]);
            } else if (u < 1536) {
                int b2 = u - 512;
                int mg = b2 & 1;
                int n  = (b2 >> 1) * 2 + nn;
                EA[(mg * 32 + m) * 1024 + n] = v + sc_b1[n];
            } else {
                int b2 = u - 1536;
                int mg = b2 & 1;
                int n  = (b2 >> 1) * 2 + nn;
                EB[(mg * 32 + m) * 1024 + n] = v;
            }
        }
        __syncthreads();
    }
    grid_sync(0);

    // ---------------- P1: enc2 -> Z (256 units) ----------------------------
    for (int u = bid; u < 256; u += NBLK) {
        int n = u * 2 + ns;
        float val = splitk_warp<256>(T1 + s * 256, 1024, enc_w2 + n * 1024 + s * 256, lane);
        pool[warp * 33 + lane] = val;
        __syncthreads();
        if (tid < 64) {
            int m = tid & 31, nn = tid >> 5;
            float v = pool[(nn * 4 + 0) * 33 + m] + pool[(nn * 4 + 1) * 33 + m]
                    + pool[(nn * 4 + 2) * 33 + m] + pool[(nn * 4 + 3) * 33 + m];
            int n2 = u * 2 + nn;
            Z[m * 512 + n2] = v + enc_b2[n2];
        }
        __syncthreads();
    }
    grid_sync(1);

    // ---------------- P2: GI (768 units) -----------------------------------
    for (int u = bid; u < 768; u += NBLK) {
        int n = u * 2 + ns;
        const float* Asl = (s < 2) ? (Z + s * 256) : (action + (s - 2) * 256);
        float val = splitk_warp<256>(Asl, 512, gru_wih + n * 1024 + s * 256, lane);
        pool[warp * 33 + lane] = val;
        __syncthreads();
        if (tid < 64) {
            int m = tid & 31, nn = tid >> 5;
            float v = pool[(nn * 4 + 0) * 33 + m] + pool[(nn * 4 + 1) * 33 + m]
                    + pool[(nn * 4 + 2) * 33 + m] + pool[(nn * 4 + 3) * 33 + m];
            int n2 = u * 2 + nn;
            GI[m * 1536 + n2] = v + gru_bih[n2];
        }
        __syncthreads();
    }
    grid_sync(2);

    // ---------------- P3: GRU pointwise (h0=0 => gh=bhh, h=(1-u)*n) --------
    {
        int i = bid * 256 + tid;
        if (i < NB * ND) {
            int b = i >> 9, d = i & 511;
            const float* gi = GI + b * 1536;
            float r  = sigmoid_acc(gi[d]        + gru_bhh[d]);
            float uu = sigmoid_acc(gi[512 + d]  + gru_bhh[512 + d]);
            float nn = tanhf(gi[1024 + d] + r * gru_bhh[1024 + d]);
            float h  = (1.0f - uu) * nn;
            H[i] = h;
            out_h[i] = h;
            HA[i] = h + action[i];
        }
    }
    grid_sync(3);

    // ---------------- P4: dec (384) + rs1 (256) + CC (512) = 1152 ----------
    for (int u = bid; u < 1152; u += NBLK) {
        float val;
        if (u < 384) {
            int n = u * 2 + ns;
            val = splitk_warp<128>(H + s * 128, 512, dec_w + n * 512 + s * 128, lane);
        } else if (u < 640) {
            int n = (u - 384) * 2 + ns;
            val = splitk_warp<128>(H + s * 128, 512, rs_w1 + n * 512 + s * 128, lane);
        } else {
            int n = (u - 640) * 2 + ns;
            val = splitk_warp<128>(HA + s * 128, 512, sc_w1 + n * 1536 + 1024 + s * 128, lane);
        }
        pool[warp * 33 + lane] = val;
        __syncthreads();
        if (tid < 64) {
            int m = tid & 31, nn = tid >> 5;
            float v = pool[(nn * 4 + 0) * 33 + m] + pool[(nn * 4 + 1) * 33 + m]
                    + pool[(nn * 4 + 2) * 33 + m] + pool[(nn * 4 + 3) * 33 + m];
            if (u < 384) {
                int n = u * 2 + nn;
                out_pred[m * 768 + n] = v + dec_b[n];
            } else if (u < 640) {
                int n = (u - 384) * 2 + nn;
                R1[m * 512 + n] = gelu_exact(v + rs_b1[n]);
            } else {
                int n = (u - 640) * 2 + nn;
                CC[m * 1024 + n] = v;
            }
        }
        __syncthreads();
    }
    grid_sync(4);

    // ---------------- P4b: dots da/db/dc (160 warp-dots of length 1024) ----
    // da[i] = sum 0.5*w2*EA[i,:]; db[j] = ...EB; dc[b] = ...CC.
    {
        int gw = bid * 8 + warp;            // blocks 0..19 carry 160 warps
        if (gw < 160) {
            const float* src;
            float* dst;
            if (gw < 64)       { src = EA + gw * 1024;         dst = DA + gw; }
            else if (gw < 128) { src = EB + (gw - 64) * 1024;  dst = DB + (gw - 64); }
            else               { src = CC + (gw - 128) * 1024; dst = DC + (gw - 128); }
            float sacc = 0.f;
            for (int d = lane; d < 1024; d += 32)
                sacc = fmaf(0.5f * sc_w2[d], src[d], sacc);
            #pragma unroll
            for (int off = 16; off > 0; off >>= 1)
                sacc += __shfl_xor_sync(0xffffffffu, sacc, off);
            if (lane == 0) *dst = sacc;
        }
    }
    grid_sync(5);

    // ---------------- P5: score (256 units, 8 rows) + rs2 (256 units) ------
    // score unit u<256: b = u>>3, i0 = (u&7)*8. warp -> one i-row; thread
    // owns j-pair (2*lane, 2*lane+1) via one LDS.64 (sE pitch 66).
    // acc = sum_d 0.5*w2*x*tanh(t(x)); logit = acc + da[i]+db[j]+dc[b] + b2.
    float* sE  = pool;                          // [dd][j] 128 x SE_PITCH
    float* sA8 = pool + 128 * SE_PITCH;         // [8][128]
    float* sW  = pool + 128 * SE_PITCH + 1024;  // [128]

    const float C0 = 0.79788456080286536f;   // sqrt(2/pi)
    const float C1 = 0.03567740813636141f;   // sqrt(2/pi)*0.044715

    for (int u = bid; u < 512; u += NBLK) {
        if (u < 256) {
            const int b   = u >> 3;
            const int i0  = (u & 7) * 8;
            const int row = i0 + warp;
            const int jp  = lane * 2;

            float acca = 0.f, accb = 0.f;

            for (int d0 = 0; d0 < 1024; d0 += 128) {
                for (int idx = tid; idx < 64 * 128; idx += 256) {
                    int j = idx >> 7, dd = idx & 127;
                    sE[dd * SE_PITCH + j] = EB[j * 1024 + d0 + dd];
                }
                for (int idx = tid; idx < 8 * 128; idx += 256) {
                    int r = idx >> 7, dd = idx & 127;
                    sA8[r * 128 + dd] = EA[(i0 + r) * 1024 + d0 + dd]
                                      + CC[b * 1024 + d0 + dd];
                }
                if (tid < 128) sW[tid] = 0.5f * sc_w2[d0 + tid];
                __syncthreads();

                #pragma unroll 4
                for (int dd = 0; dd < 128; dd++) {
                    float2 e = *reinterpret_cast<const float2*>(&sE[dd * SE_PITCH + jp]);
                    float a  = sA8[warp * 128 + dd];
                    float w  = sW[dd];

                    float xa = a + e.x, xb = a + e.y;
                    float ta = xa * fmaf(C1, xa * xa, C0);
                    float tb = xb * fmaf(C1, xb * xb, C0);
                    float ha = tanh_approx(ta);
                    float hb = tanh_approx(tb);
                    acca = fmaf(w * xa, ha, acca);
                    accb = fmaf(w * xb, hb, accb);
                }
                __syncthreads();
            }

            const float base = DC[b] + DA[row] + sc_b2[0];
            float sa = sigmoid_acc(acca + base + DB[jp])     * (1.0f / 32.0f);
            float sb = sigmoid_acc(accb + base + DB[jp + 1]) * (1.0f / 32.0f);
            atomicAdd(&out_graph[row * 64 + jp],     sa);
            atomicAdd(&out_graph[row * 64 + jp + 1], sb);
        } else {
            // rs2 unit
            int n = (u - 256) * 2 + ns;
            float val = splitk_warp<128>(R1 + s * 128, 512, rs_w2 + n * 512 + s * 128, lane);
            pool[warp * 33 + lane] = val;
            __syncthreads();
            if (tid < 64) {
                int m = tid & 31, nn = tid >> 5;
                float v = pool[(nn * 4 + 0) * 33 + m] + pool[(nn * 4 + 1) * 33 + m]
                        + pool[(nn * 4 + 2) * 33 + m] + pool[(nn * 4 + 3) * 33 + m];
                int n2 = (u - 256) * 2 + nn;
                out_reason[m * 512 + n2] = v + rs_b2[n2];
            }
            __syncthreads();
        }
    }
}

// ---------------------------------------------------------------------------
extern "C" void kernel_launch(void* const* d_in, const int* in_sizes, int n_in,
                              void* d_out, int out_size)
{
    float* S = nullptr;
    cudaGetSymbolAddress((void**)&S, g_scratch);

    const float* obs     = (const float*)d_in[0];
    const float* action  = (const float*)d_in[1];
    const float* embed   = (const float*)d_in[2];
    const float* sc_w1   = (const float*)d_in[3];
    const float* sc_b1   = (const float*)d_in[4];
    const float* sc_w2   = (const float*)d_in[5];
    const float* sc_b2   = (const float*)d_in[6];
    const float* enc_w1  = (const float*)d_in[7];
    const float* enc_b1  = (const float*)d_in[8];
    const float* enc_w2  = (const float*)d_in[9];
    const float* enc_b2  = (const float*)d_in[10];
    const float* gru_wih = (const float*)d_in[11];
    // d_in[12] gru_whh unused (h0 == 0)
    const float* gru_bih = (const float*)d_in[13];
    const float* gru_bhh = (const float*)d_in[14];
    const float* dec_w   = (const float*)d_in[15];
    const float* dec_b   = (const float*)d_in[16];
    const float* rs_w1   = (const float*)d_in[17];
    const float* rs_b1   = (const float*)d_in[18];
    const float* rs_w2   = (const float*)d_in[19];
    const float* rs_b2   = (const float*)d_in[20];

    float* out        = (float*)d_out;
    float* out_h      = out;
    float* out_pred   = out + 16384;
    float* out_graph  = out + 16384 + 24576;
    float* out_reason = out + 16384 + 24576 + 4096;

    float* T1 = S + OFF_T1;
    float* Z  = S + OFF_Z;
    float* GI = S + OFF_GI;
    float* H  = S + OFF_H;
    float* HA = S + OFF_HA;
    float* CC = S + OFF_CC;
    float* EA = S + OFF_EA;
    float* EB = S + OFF_EB;
    float* R1 = S + OFF_R1;
    float* DA = S + OFF_DA;
    float* DB = S + OFF_DB;
    float* DC = S + OFF_DC;

    mega_kernel<<<NBLK, 256>>>(
        obs, action, embed,
        sc_w1, sc_b1, sc_w2, sc_b2,
        enc_w1, enc_b1, enc_w2, enc_b2,
        gru_wih, gru_bih, gru_bhh,
        dec_w, dec_b, rs_w1, rs_b1, rs_w2, rs_b2,
        T1, Z, GI, H, HA, CC, EA, EB, R1, DA, DB, DC,
        out_h, out_pred, out_graph, out_reason);
}